// round 14
// baseline (speedup 1.0000x reference)
#include <cuda_runtime.h>
#include <cstdint>
#include <cstddef>

#define Lc 1024
#define Bc 8192

// tab[i*256 + m]       = (E0-E1)[i][m] * A_i[m]   (EDA0), A_i = prod_{j<i} E0_j
// tab[i*256 + 128 + m] = (E1/E0)[i][m]            (R)
__device__ __align__(16) float    g_tab[Lc * 256];
// xpack[w*Bc + b] = bitmask of inputs[b, 32w .. 32w+31]
__device__ __align__(16) uint32_t g_xpack[(Lc / 32) * Bc];

// merged prep (ONE launch): block 0 builds the EDA0/R tables via a two-phase
// prefix-product scan; blocks 1..256 pack inputs into bitmasks.
__global__ __launch_bounds__(1024)
void prep_all(const float* __restrict__ eps, const int* __restrict__ x) {
    if (blockIdx.x == 0) {
        __shared__ float P[8][128];
        const int t   = threadIdx.x;
        const int m   = t & 127;
        const int seg = t >> 7;                    // 8 segments of 128 steps
        const float* e0p = eps + (size_t)m * Lc;            // eps[0][m][i]
        const float* e1p = eps + (size_t)(128 + m) * Lc;    // eps[1][m][i]
        const int i0 = seg * 128;
        // pass 1: per-segment product of E0
        float p = 1.0f;
#pragma unroll 4
        for (int i = 0; i < 128; i++) p *= e0p[i0 + i];
        P[seg][m] = p;
        __syncthreads();
        // pass 2: prefix over earlier segments, then walk this segment
        float A = 1.0f;
        for (int s = 0; s < seg; s++) A *= P[s][m];
#pragma unroll 2
        for (int i = 0; i < 128; i++) {
            const int ii = i0 + i;
            const float e0 = e0p[ii], e1 = e1p[ii];
            g_tab[ii * 256 + m]       = (e0 - e1) * A;   // EDA0 (A exclusive of ii)
            g_tab[ii * 256 + 128 + m] = e1 / e0;         // R
            A *= e0;
        }
    } else {
        const int b = (blockIdx.x - 1) * 32 + (threadIdx.x >> 5);
        const int k = threadIdx.x & 31;
#pragma unroll 4
        for (int w = 0; w < 32; w++) {
            int v = x[(size_t)b * Lc + (w << 5) + k];
            unsigned msk = __ballot_sync(0xffffffffu, v != 0);
            if (k == 0) g_xpack[w * Bc + b] = msk;
        }
    }
}

static __device__ __forceinline__ uint64_t mul2(uint64_t a, uint64_t b) {
    uint64_t d; asm("mul.rn.f32x2 %0, %1, %2;" : "=l"(d) : "l"(a), "l"(b)); return d;
}
static __device__ __forceinline__ uint64_t fma2(uint64_t a, uint64_t b, uint64_t c) {
    uint64_t d; asm("fma.rn.f32x2 %0, %1, %2, %3;" : "=l"(d) : "l"(a), "l"(b), "l"(c)); return d;
}
static __device__ __forceinline__ float hadd2(uint64_t v) {
    float x, y; asm("mov.b64 {%0,%1}, %2;" : "=f"(x), "=f"(y) : "l"(v)); return x + y;
}
static __device__ __forceinline__ float ex2f(float x) {
    float y; asm("ex2.approx.ftz.f32 %0, %1;" : "=f"(y) : "f"(x)); return y;
}
static __device__ __forceinline__ float lg2f(float x) {
    float y; asm("lg2.approx.ftz.f32 %0, %1;" : "=f"(y) : "f"(x)); return y;
}

// predicated B-update: if (bit) { bx *= rx; by *= ry; }  (no SELs, 3 issues)
static __device__ __forceinline__ void bupd(uint64_t& bx, uint64_t& by,
                                            uint32_t bit, uint64_t rx, uint64_t ry) {
    asm("{\n\t"
        ".reg .pred p;\n\t"
        "setp.ne.u32 p, %2, 0;\n\t"
        "@p mul.rn.f32x2 %0, %0, %3;\n\t"
        "@p mul.rn.f32x2 %1, %1, %4;\n\t"
        "}"
        : "+l"(bx), "+l"(by) : "r"(bit), "l"(rx), "l"(ry));
}

// fold 8 step-partials across lane groups + term for this lane's (batch, step)
static __device__ __forceinline__ void fold_term(
    const float* uu, uint32_t pxq0, int pK8, int pibase, int pcnt0,
    int js, bool h4, bool h8, bool h16, float& acc)
{
    float a0, a1, a2, a3, s;
    a0 = h4 ? uu[1] : uu[0]; s = h4 ? uu[0] : uu[1];
    a0 += __shfl_xor_sync(0xffffffffu, s, 4);
    a1 = h4 ? uu[3] : uu[2]; s = h4 ? uu[2] : uu[3];
    a1 += __shfl_xor_sync(0xffffffffu, s, 4);
    a2 = h4 ? uu[5] : uu[4]; s = h4 ? uu[4] : uu[5];
    a2 += __shfl_xor_sync(0xffffffffu, s, 4);
    a3 = h4 ? uu[7] : uu[6]; s = h4 ? uu[6] : uu[7];
    a3 += __shfl_xor_sync(0xffffffffu, s, 4);
    float c0, c1;
    c0 = h8 ? a1 : a0; s = h8 ? a0 : a1;
    c0 += __shfl_xor_sync(0xffffffffu, s, 8);
    c1 = h8 ? a3 : a2; s = h8 ? a2 : a3;
    c1 += __shfl_xor_sync(0xffffffffu, s, 8);
    float c = h16 ? c1 : c0; s = h16 ? c0 : c1;
    c += __shfl_xor_sync(0xffffffffu, s, 16);
    // c = full-128m delta (s0 - s1) for (batch l&3, step pibase + pK8 + js)

    const int  kk = pK8 + js;
    const int  i  = pibase + kk;
    const bool x1 = ((pxq0 >> kk) & 1u) != 0;
    const int  zb = __popc((~pxq0) & ((1u << kk) - 1u));
    const int  cnt0 = pcnt0 + zb;

    const float t    = x1 ? c : -c;
    const float relu = fmaxf(t, 0.0f);
    const float z    = ex2f(fabsf(c) * -2.8853902f);
    float term = -relu - 0.34657359f * lg2f(1.0f + z);

    const int cOther = x1 ? cnt0 : (i - cnt0);
    if (cOther >= 512) term = 0.0f;
    acc += term;
}

__global__ __launch_bounds__(32, 14)
void arqgps_main(float* __restrict__ out) {
    const int l    = threadIdx.x;        // 1 warp = 4 batches
    const int b0   = blockIdx.x * 4;
    const int perm = l & 3;              // slot sp tracks batch sp^perm; term-batch = perm
    const int js   = l >> 2;             // lane's step-offset within each 8-step block
    const bool h4  = (l & 4)  != 0;
    const bool h8  = (l & 8)  != 0;
    const bool h16 = (l & 16) != 0;

    const uint64_t ONE2 = 0x3f8000003f800000ull;

    // per-slot B state (batch-dependent part of g): 4 m in 2 f32x2
    uint64_t bx[4], by[4];
#pragma unroll
    for (int sp = 0; sp < 4; sp++) { bx[sp] = ONE2; by[sp] = ONE2; }

    float acc       = 0.0f;
    int   cnt0_base = 0;

    // pipeline state: previous block's partials + its term context
    float    u_prev[8];
    uint32_t pxq0   = 0;
    int      pK8    = 0, pibase = 0, pcnt0 = 0;
    bool     started = false;

    const ulonglong2* dpp = (const ulonglong2*)g_tab + l;     // EDA0, m 4l..4l+3
    const ulonglong2* rpp = dpp + 32;                         // R

    for (int w = 0; w < Lc / 32; w++) {
        const uint32_t xq0 = __ldg(g_xpack + w * Bc + b0 + (0 ^ perm));
        const uint32_t xq1 = __ldg(g_xpack + w * Bc + b0 + (1 ^ perm));
        const uint32_t xq2 = __ldg(g_xpack + w * Bc + b0 + (2 ^ perm));
        const uint32_t xq3 = __ldg(g_xpack + w * Bc + b0 + (3 ^ perm));

#pragma unroll
        for (int kb = 0; kb < 4; kb++) {
            const int K8 = kb << 3;
            const uint32_t x0w = xq0 >> K8;
            const uint32_t x1w = xq1 >> K8;
            const uint32_t x2w = xq2 >> K8;
            const uint32_t x3w = xq3 >> K8;

            // ---- front-batched loads for this 8-step block (MLP 16) ----
            ulonglong2 Dv[8], Rv[8];
#pragma unroll
            for (int j = 0; j < 8; j++) {
                const size_t i = (size_t)((w << 5) + K8 + j) * 64;
                Dv[j] = __ldg(dpp + i);
                Rv[j] = __ldg(rpp + i);
            }

            float u_cur[8];
#pragma unroll
            for (int j = 0; j < 8; j++) {
                const ulonglong2 D = Dv[j];      // EDA0 for 4 m (x: m0m1, y: m2m3)
                const ulonglong2 R = Rv[j];

                const uint32_t bj = 1u << j;

                // delta partials: EDA0 . B  (per slot)
                uint64_t pd0 = fma2(D.y, by[0], mul2(D.x, bx[0]));
                uint64_t pd1 = fma2(D.y, by[1], mul2(D.x, bx[1]));
                uint64_t pd2 = fma2(D.y, by[2], mul2(D.x, bx[2]));
                uint64_t pd3 = fma2(D.y, by[3], mul2(D.x, bx[3]));

                // B-update (after dot): B *= R when this slot's x-bit is set
                bupd(bx[0], by[0], x0w & bj, R.x, R.y);
                bupd(bx[1], by[1], x1w & bj, R.x, R.y);
                bupd(bx[2], by[2], x2w & bj, R.x, R.y);
                bupd(bx[3], by[3], x3w & bj, R.x, R.y);

                float v0 = hadd2(pd0);
                float v1 = hadd2(pd1);
                float v2 = hadd2(pd2);
                float v3 = hadd2(pd3);

                // slot-combine: v0 = 16-m partial delta for batch (l&3)
                v0 += __shfl_xor_sync(0xffffffffu, v2, 2);
                v1 += __shfl_xor_sync(0xffffffffu, v3, 2);
                v0 += __shfl_xor_sync(0xffffffffu, v1, 1);
                u_cur[j] = v0;
            }

            // ---- deferred fold+term of the PREVIOUS block ----
            if (started)
                fold_term(u_prev, pxq0, pK8, pibase, pcnt0,
                          js, h4, h8, h16, acc);

#pragma unroll
            for (int j = 0; j < 8; j++) u_prev[j] = u_cur[j];
            pxq0 = xq0; pK8 = K8; pibase = w << 5; pcnt0 = cnt0_base;
            started = true;
        }

        cnt0_base += 32 - __popc(xq0);
    }

    // epilogue: fold+term of the final block
    fold_term(u_prev, pxq0, pK8, pibase, pcnt0, js, h4, h8, h16, acc);

    acc += __shfl_xor_sync(0xffffffffu, acc, 4);
    acc += __shfl_xor_sync(0xffffffffu, acc, 8);
    acc += __shfl_xor_sync(0xffffffffu, acc, 16);

    if (l < 4)
        out[b0 + l] = acc;
}

extern "C" void kernel_launch(void* const* d_in, const int* in_sizes, int n_in,
                              void* d_out, int out_size) {
    (void)n_in; (void)out_size;
    const int*   inputs;
    const float* eps;
    if (in_sizes[0] == Bc * Lc) {
        inputs = (const int*)d_in[0];
        eps    = (const float*)d_in[1];
    } else {
        inputs = (const int*)d_in[1];
        eps    = (const float*)d_in[0];
    }
    float* out = (float*)d_out;

    prep_all<<<257, 1024>>>(eps, inputs);
    arqgps_main<<<Bc / 4, 32>>>(out);
}

// round 17
// speedup vs baseline: 1.6669x; 1.6669x over previous
#include <cuda_runtime.h>
#include <cstdint>
#include <cstddef>

#define Lc 1024
#define Bc 8192

// tab[i*256 + m]       = (E0-E1)[i][m] * A_i[m]   (EDA0), A_i = prod_{j<i} E0_j[m]
// tab[i*256 + 128 + m] = (E1/E0)[i][m]            (R)
__device__ __align__(16) float    g_tab[Lc * 256];
// xpack[w*Bc + b] = bitmask of inputs[b, 32w .. 32w+31]
__device__ __align__(16) uint32_t g_xpack[(Lc / 32) * Bc];
// segprod[seg*128 + m] = prod of E0 over steps [seg*32, seg*32+32)
__device__ __align__(16) float    g_segprod[32 * 128];

// prepA: blocks 0..3 -> segment products of E0 (4096 (m,seg) pairs);
//        blocks 4..259 -> pack inputs into bitmasks.
__global__ __launch_bounds__(1024)
void prepA(const float* __restrict__ eps, const int* __restrict__ x) {
    if (blockIdx.x < 4) {
        const int idx = blockIdx.x * 1024 + threadIdx.x;   // (m, seg) pair
        const int m   = idx & 127;
        const int seg = idx >> 7;                          // 0..31
        const float* e0p = eps + (size_t)m * Lc + seg * 32;
        float p = 1.0f;
#pragma unroll
        for (int i = 0; i < 32; i++) p *= e0p[i];
        g_segprod[seg * 128 + m] = p;
    } else {
        const int b = (blockIdx.x - 4) * 32 + (threadIdx.x >> 5);
        const int k = threadIdx.x & 31;
#pragma unroll 4
        for (int w = 0; w < 32; w++) {
            int v = x[(size_t)b * Lc + (w << 5) + k];
            unsigned msk = __ballot_sync(0xffffffffu, v != 0);
            if (k == 0) g_xpack[w * Bc + b] = msk;
        }
    }
}

// prepB: each thread owns one (m, seg): builds its exclusive prefix from the
// segment products, then fills 32 table rows.
__global__ __launch_bounds__(1024)
void prepB(const float* __restrict__ eps) {
    const int idx = blockIdx.x * 1024 + threadIdx.x;
    const int m   = idx & 127;
    const int seg = idx >> 7;

    float A = 1.0f;
    for (int s = 0; s < seg; s++) A *= g_segprod[s * 128 + m];

    const float* e0p = eps + (size_t)m * Lc;
    const float* e1p = eps + (size_t)(128 + m) * Lc;
    const int i0 = seg * 32;
#pragma unroll 4
    for (int i = 0; i < 32; i++) {
        const int ii = i0 + i;
        const float e0 = e0p[ii], e1 = e1p[ii];
        g_tab[ii * 256 + m]       = (e0 - e1) * A;        // EDA0 (A exclusive of ii)
        g_tab[ii * 256 + 128 + m] = __fdividef(e1, e0);   // R
        A *= e0;
    }
}

static __device__ __forceinline__ uint64_t mul2(uint64_t a, uint64_t b) {
    uint64_t d; asm("mul.rn.f32x2 %0, %1, %2;" : "=l"(d) : "l"(a), "l"(b)); return d;
}
static __device__ __forceinline__ uint64_t fma2(uint64_t a, uint64_t b, uint64_t c) {
    uint64_t d; asm("fma.rn.f32x2 %0, %1, %2, %3;" : "=l"(d) : "l"(a), "l"(b), "l"(c)); return d;
}
static __device__ __forceinline__ float hadd2(uint64_t v) {
    float x, y; asm("mov.b64 {%0,%1}, %2;" : "=f"(x), "=f"(y) : "l"(v)); return x + y;
}
static __device__ __forceinline__ float ex2f(float x) {
    float y; asm("ex2.approx.ftz.f32 %0, %1;" : "=f"(y) : "f"(x)); return y;
}
static __device__ __forceinline__ float lg2f(float x) {
    float y; asm("lg2.approx.ftz.f32 %0, %1;" : "=f"(y) : "f"(x)); return y;
}

// predicated B-update: if (bit) { bx *= rx; by *= ry; }  (no SELs, 3 issues)
static __device__ __forceinline__ void bupd(uint64_t& bx, uint64_t& by,
                                            uint32_t bit, uint64_t rx, uint64_t ry) {
    asm("{\n\t"
        ".reg .pred p;\n\t"
        "setp.ne.u32 p, %2, 0;\n\t"
        "@p mul.rn.f32x2 %0, %0, %3;\n\t"
        "@p mul.rn.f32x2 %1, %1, %4;\n\t"
        "}"
        : "+l"(bx), "+l"(by) : "r"(bit), "l"(rx), "l"(ry));
}

// fold 8 step-partials across lane groups + term for this lane's (batch, step)
static __device__ __forceinline__ void fold_term(
    const float* uu, uint32_t pxq0, int pK8, int pibase, int pcnt0,
    int js, bool h4, bool h8, bool h16, float& acc)
{
    float a0, a1, a2, a3, s;
    a0 = h4 ? uu[1] : uu[0]; s = h4 ? uu[0] : uu[1];
    a0 += __shfl_xor_sync(0xffffffffu, s, 4);
    a1 = h4 ? uu[3] : uu[2]; s = h4 ? uu[2] : uu[3];
    a1 += __shfl_xor_sync(0xffffffffu, s, 4);
    a2 = h4 ? uu[5] : uu[4]; s = h4 ? uu[4] : uu[5];
    a2 += __shfl_xor_sync(0xffffffffu, s, 4);
    a3 = h4 ? uu[7] : uu[6]; s = h4 ? uu[6] : uu[7];
    a3 += __shfl_xor_sync(0xffffffffu, s, 4);
    float c0, c1;
    c0 = h8 ? a1 : a0; s = h8 ? a0 : a1;
    c0 += __shfl_xor_sync(0xffffffffu, s, 8);
    c1 = h8 ? a3 : a2; s = h8 ? a2 : a3;
    c1 += __shfl_xor_sync(0xffffffffu, s, 8);
    float c = h16 ? c1 : c0; s = h16 ? c0 : c1;
    c += __shfl_xor_sync(0xffffffffu, s, 16);
    // c = full-128m delta (s0 - s1) for (batch l&3, step pibase + pK8 + js)

    const int  kk = pK8 + js;
    const int  i  = pibase + kk;
    const bool x1 = ((pxq0 >> kk) & 1u) != 0;
    const int  zb = __popc((~pxq0) & ((1u << kk) - 1u));
    const int  cnt0 = pcnt0 + zb;

    const float t    = x1 ? c : -c;
    const float relu = fmaxf(t, 0.0f);
    const float z    = ex2f(fabsf(c) * -2.8853902f);
    float term = -relu - 0.34657359f * lg2f(1.0f + z);

    const int cOther = x1 ? cnt0 : (i - cnt0);
    if (cOther >= 512) term = 0.0f;
    acc += term;
}

__global__ __launch_bounds__(32, 14)
void arqgps_main(float* __restrict__ out) {
    const int l    = threadIdx.x;        // 1 warp = 4 batches
    const int b0   = blockIdx.x * 4;
    const int perm = l & 3;              // slot sp tracks batch sp^perm; term-batch = perm
    const int js   = l >> 2;             // lane's step-offset within each 8-step block
    const bool h4  = (l & 4)  != 0;
    const bool h8  = (l & 8)  != 0;
    const bool h16 = (l & 16) != 0;

    const uint64_t ONE2 = 0x3f8000003f800000ull;

    // per-slot B state (batch-dependent part of g): 4 m in 2 f32x2
    uint64_t bx[4], by[4];
#pragma unroll
    for (int sp = 0; sp < 4; sp++) { bx[sp] = ONE2; by[sp] = ONE2; }

    float acc       = 0.0f;
    int   cnt0_base = 0;

    // pipeline state: previous block's partials + its term context
    float    u_prev[8];
    uint32_t pxq0   = 0;
    int      pK8    = 0, pibase = 0, pcnt0 = 0;
    bool     started = false;

    const ulonglong2* dpp = (const ulonglong2*)g_tab + l;     // EDA0, m 4l..4l+3
    const ulonglong2* rpp = dpp + 32;                         // R

    for (int w = 0; w < Lc / 32; w++) {
        const uint32_t xq0 = __ldg(g_xpack + w * Bc + b0 + (0 ^ perm));
        const uint32_t xq1 = __ldg(g_xpack + w * Bc + b0 + (1 ^ perm));
        const uint32_t xq2 = __ldg(g_xpack + w * Bc + b0 + (2 ^ perm));
        const uint32_t xq3 = __ldg(g_xpack + w * Bc + b0 + (3 ^ perm));

#pragma unroll
        for (int kb = 0; kb < 4; kb++) {
            const int K8 = kb << 3;
            const uint32_t x0w = xq0 >> K8;
            const uint32_t x1w = xq1 >> K8;
            const uint32_t x2w = xq2 >> K8;
            const uint32_t x3w = xq3 >> K8;

            // ---- front-batched loads for this 8-step block (MLP 16) ----
            ulonglong2 Dv[8], Rv[8];
#pragma unroll
            for (int j = 0; j < 8; j++) {
                const size_t i = (size_t)((w << 5) + K8 + j) * 64;
                Dv[j] = __ldg(dpp + i);
                Rv[j] = __ldg(rpp + i);
            }

            float u_cur[8];
#pragma unroll
            for (int j = 0; j < 8; j++) {
                const ulonglong2 D = Dv[j];      // EDA0 for 4 m (x: m0m1, y: m2m3)
                const ulonglong2 R = Rv[j];

                const uint32_t bj = 1u << j;

                // delta partials: EDA0 . B  (per slot)
                uint64_t pd0 = fma2(D.y, by[0], mul2(D.x, bx[0]));
                uint64_t pd1 = fma2(D.y, by[1], mul2(D.x, bx[1]));
                uint64_t pd2 = fma2(D.y, by[2], mul2(D.x, bx[2]));
                uint64_t pd3 = fma2(D.y, by[3], mul2(D.x, bx[3]));

                // B-update (after dot): B *= R when this slot's x-bit is set
                bupd(bx[0], by[0], x0w & bj, R.x, R.y);
                bupd(bx[1], by[1], x1w & bj, R.x, R.y);
                bupd(bx[2], by[2], x2w & bj, R.x, R.y);
                bupd(bx[3], by[3], x3w & bj, R.x, R.y);

                float v0 = hadd2(pd0);
                float v1 = hadd2(pd1);
                float v2 = hadd2(pd2);
                float v3 = hadd2(pd3);

                // slot-combine: v0 = 16-m partial delta for batch (l&3)
                v0 += __shfl_xor_sync(0xffffffffu, v2, 2);
                v1 += __shfl_xor_sync(0xffffffffu, v3, 2);
                v0 += __shfl_xor_sync(0xffffffffu, v1, 1);
                u_cur[j] = v0;
            }

            // ---- deferred fold+term of the PREVIOUS block ----
            if (started)
                fold_term(u_prev, pxq0, pK8, pibase, pcnt0,
                          js, h4, h8, h16, acc);

#pragma unroll
            for (int j = 0; j < 8; j++) u_prev[j] = u_cur[j];
            pxq0 = xq0; pK8 = K8; pibase = w << 5; pcnt0 = cnt0_base;
            started = true;
        }

        cnt0_base += 32 - __popc(xq0);
    }

    // epilogue: fold+term of the final block
    fold_term(u_prev, pxq0, pK8, pibase, pcnt0, js, h4, h8, h16, acc);

    acc += __shfl_xor_sync(0xffffffffu, acc, 4);
    acc += __shfl_xor_sync(0xffffffffu, acc, 8);
    acc += __shfl_xor_sync(0xffffffffu, acc, 16);

    if (l < 4)
        out[b0 + l] = acc;
}

extern "C" void kernel_launch(void* const* d_in, const int* in_sizes, int n_in,
                              void* d_out, int out_size) {
    (void)n_in; (void)out_size;
    const int*   inputs;
    const float* eps;
    if (in_sizes[0] == Bc * Lc) {
        inputs = (const int*)d_in[0];
        eps    = (const float*)d_in[1];
    } else {
        inputs = (const int*)d_in[1];
        eps    = (const float*)d_in[0];
    }
    float* out = (float*)d_out;

    prepA<<<260, 1024>>>(eps, inputs);
    prepB<<<4, 1024>>>(eps);
    arqgps_main<<<Bc / 4, 32>>>(out);
}